// round 14
// baseline (speedup 1.0000x reference)
#include <cuda_runtime.h>
#include <cuda_fp16.h>

// ---------------------------------------------------------------------------
// SSIM fusion loss: 1 - (SSIM(f,s1)+SSIM(f,s2))/2, single fused kernel.
// 5 CTAs/SM. Halo builds 4 half2 field-pair planes once per pixel (fp32
// products -> fp16). hpass: HADD2/HFMA2 symmetric 11-tap blur (plane-major
// raw). hint stored group-interleaved [2 grp][36 col][2 pair] so the vpass
// uses conflict-free LDS.64 (half the LSU instrs). Bit-exact vs R13.
// ---------------------------------------------------------------------------

#define IMH 512
#define IMW 512
#define TW 32
#define TH 32
#define EXT 42
#define RP 44                    // cols per raw pair-plane (half2 units)
#define RROW 176                 // raw row stride in half2 = 4*RP
#define HROW2 144                // hint row stride in half2 (2 groups * 72)
#define GST2 72                  // half2 per group within a hint row (36 cols * 2)
#define R1 24                    // phase-A hint rows (0..23)
#define RAW_H2 (EXT*RROW)        // 7392 half2 = 29568 B
#define NTHREADS 256
#define GX 16
#define GY 16
#define NPLANES 48
#define NBLOCKS (GX*GY*NPLANES)
#define NTOT 12582912.0
#define FPSCALE 4294967296.0
#define SMEM_BYTES (RAW_H2*4 + R1*HROW2*4)   // 29568 + 13824 = 43392 B

typedef unsigned long long u64;

__device__ u64      g_accs[NPLANES];
__device__ unsigned g_count = 0u;

// Gaussian weights (sigma=1.5, 11 taps, normalized) as pure literals.
#define W0f 0.00102838f
#define W1f 0.00759876f
#define W2f 0.03600077f
#define W3f 0.10936069f
#define W4f 0.21300554f
#define W5f 0.26601173f
#define WW(j) ( (j)==5 ? W5f : ((j)==4||(j)==6) ? W4f : ((j)==3||(j)==7) ? W3f \
              : ((j)==2||(j)==8) ? W2f : ((j)==1||(j)==9) ? W1f : W0f )

// half2 11-tap horizontal blur of one raw row. Planes processed in groups of
// two; per-plane math identical (same rounding order) to the plane-major
// version. Stores column-interleaved: group g, col c -> hint[g*72 + c*2 + pp].
#define HPASS_H2(RAWBASE, HBASE)                                              \
{                                                                             \
    _Pragma("unroll")                                                         \
    for (int g = 0; g < 2; ++g) {                                             \
        __half2 accg[2][4];                                                   \
        _Pragma("unroll")                                                     \
        for (int pp = 0; pp < 2; ++pp) {                                      \
            const int p = 2*g + pp;                                           \
            __half2 v[16];                                                    \
            _Pragma("unroll")                                                 \
            for (int k = 0; k < 4; ++k)                                       \
                *reinterpret_cast<uint4*>(&v[4*k]) =                          \
                    *reinterpret_cast<const uint4*>(&raw2[(RAWBASE) + p*RP + c0 + 4*k]); \
            _Pragma("unroll")                                                 \
            for (int o = 0; o < 4; ++o) {                                     \
                __half2 s = __hmul2(wh[0], __hadd2(v[o+0], v[o+10]));         \
                _Pragma("unroll")                                             \
                for (int j = 1; j < 5; ++j)                                   \
                    s = __hfma2(wh[j], __hadd2(v[o+j], v[o+10-j]), s);        \
                accg[pp][o] = __hfma2(wh[5], v[o+5], s);                      \
            }                                                                 \
        }                                                                     \
        uint4 s0, s1;                                                         \
        s0.x = *reinterpret_cast<unsigned*>(&accg[0][0]);                     \
        s0.y = *reinterpret_cast<unsigned*>(&accg[1][0]);                     \
        s0.z = *reinterpret_cast<unsigned*>(&accg[0][1]);                     \
        s0.w = *reinterpret_cast<unsigned*>(&accg[1][1]);                     \
        s1.x = *reinterpret_cast<unsigned*>(&accg[0][2]);                     \
        s1.y = *reinterpret_cast<unsigned*>(&accg[1][2]);                     \
        s1.z = *reinterpret_cast<unsigned*>(&accg[0][3]);                     \
        s1.w = *reinterpret_cast<unsigned*>(&accg[1][3]);                     \
        *reinterpret_cast<uint4*>(&hintS[(HBASE) + g*GST2 + (c0+0)*2]) = s0;  \
        *reinterpret_cast<uint4*>(&hintS[(HBASE) + g*GST2 + (c0+2)*2]) = s1;  \
    }                                                                         \
}

// vpass accumulation over 14 hint rows starting at r0v. Loads one LDS.64 per
// group (conflict-free); v[] values and accumulation order identical to R13.
#define VPASS_LOOP(ROWPTR)                                                    \
    _Pragma("unroll")                                                         \
    for (int jj = 0; jj < 14; ++jj) {                                         \
        const int row = r0v + jj;                                             \
        const __half2* rowp = ROWPTR(row);                                    \
        uint2 g0 = *reinterpret_cast<const uint2*>(&rowp[0*GST2 + col*2]);    \
        uint2 g1 = *reinterpret_cast<const uint2*>(&rowp[1*GST2 + col*2]);    \
        __half2 v[4];                                                         \
        v[0] = *reinterpret_cast<__half2*>(&g0.x);                            \
        v[1] = *reinterpret_cast<__half2*>(&g0.y);                            \
        v[2] = *reinterpret_cast<__half2*>(&g1.x);                            \
        v[3] = *reinterpret_cast<__half2*>(&g1.y);                            \
        _Pragma("unroll")                                                     \
        for (int o = 0; o < 4; ++o) {                                         \
            const int j = jj - o;                                             \
            if (j >= 0 && j < 11) {                                           \
                const __half2 w = wh[(j < 6) ? j : (10 - j)];                 \
                _Pragma("unroll")                                             \
                for (int p = 0; p < 4; ++p)                                   \
                    acc[p][o] = __hfma2(w, v[p], acc[p][o]);                  \
            }                                                                 \
        }                                                                     \
    }

__global__ __launch_bounds__(NTHREADS, 5)
void ssim_fused_kernel(const float* __restrict__ F,
                       const float* __restrict__ S1,
                       const float* __restrict__ S2,
                       float* __restrict__ out)
{
    extern __shared__ float smemf[];
    __half2* raw2   = reinterpret_cast<__half2*>(smemf);      // [42][4][44]
    __half2* hint2A = raw2 + RAW_H2;                          // rows 0..23
    __half2* hint2B = raw2;                                   // rows 24..41 (alias)

    const int tid  = threadIdx.x;
    const int wid  = tid >> 5;
    const int lane = tid & 31;

    const int bx = blockIdx.x, by = blockIdx.y, bz = blockIdx.z;
    const int plane = bz * (IMH * IMW);
    const int y0 = by * TH - 5;

    // fp16 (w,w) weights, 6 unique — used by both passes
    __half2 wh[6];
    #pragma unroll
    for (int j = 0; j < 6; ++j) wh[j] = __floats2half2_rn(WW(j), WW(j));

    // ---- Halo load: 42 rows x 12 float4 chunks; build 4 half2 pair-planes -
    for (int i = tid; i < EXT * 12; i += NTHREADS) {
        const int q  = i % 12;
        const int r  = i / 12;
        const int gy = y0 + r;
        const int gx0 = bx * TW - 8 + q * 4;
        const bool ok = (gy >= 0) && (gy < IMH) && (gx0 >= 0) && (gx0 <= IMW - 4);

        float4 vf = make_float4(0.f,0.f,0.f,0.f);
        float4 va = vf, vb = vf;
        if (ok) {
            const int off = plane + gy * IMW + gx0;
            vf = *reinterpret_cast<const float4*>(F  + off);
            va = *reinterpret_cast<const float4*>(S1 + off);
            vb = *reinterpret_cast<const float4*>(S2 + off);
        }
        const float ff[4] = {vf.x, vf.y, vf.z, vf.w};
        const float fa[4] = {va.x, va.y, va.z, va.w};
        const float fb[4] = {vb.x, vb.y, vb.z, vb.w};

        const int cb = q * 4 - 3;
        #pragma unroll
        for (int t = 0; t < 4; ++t) {
            const int c = cb + t;
            if (c >= 0 && c < EXT) {
                const float f = ff[t], a = fa[t], b = fb[t];
                __half2 h0  = __floats2half2_rn(f, a);
                __half2 h1  = __floats2half2_rn(b, f * f);
                __half2 hab = __floats2half2_rn(a, b);
                __half2 hff = __floats2half2_rn(f, f);
                __half2 h2  = __hmul2(hab, hab);
                __half2 h3  = __hmul2(hff, hab);
                raw2[r*RROW + 0*RP + c] = h0;
                raw2[r*RROW + 1*RP + c] = h1;
                raw2[r*RROW + 2*RP + c] = h2;
                raw2[r*RROW + 3*RP + c] = h3;
            }
        }
    }
    __syncthreads();

    // ---- Horizontal pass, phase A: rows 0..23 -> hintA --------------------
    if (tid < R1 * 8) {
        const int r  = tid >> 3;
        const int c0 = (tid & 7) * 4;
        __half2* hintS = hint2A;
        HPASS_H2(r * RROW, r * HROW2)
    }
    __syncthreads();

    // ---- Phase B: rows 24..41 -> hintB at smem[0] (overlays raw rows <=17)
    if (tid < (EXT - R1) * 8) {
        const int rr = tid >> 3;            // 0..17 -> row 24+rr
        const int c0 = (tid & 7) * 4;
        __half2* hintS = hint2B;
        HPASS_H2((R1 + rr) * RROW, rr * HROW2)
    }
    __syncthreads();

    // ---- Vertical pass (half2/HFMA2) + SSIM: thread = 1 col x 4 rows ------
    const int col = lane;
    const int r0v = wid * 4;

    __half2 acc[4][4];  // [pair][out]
    #pragma unroll
    for (int p = 0; p < 4; ++p)
        #pragma unroll
        for (int o = 0; o < 4; ++o) acc[p][o] = __floats2half2_rn(0.f, 0.f);

    #define ROWPTR_A(row)   (&hint2A[(row) * HROW2])
    #define ROWPTR_MIX(row) ((row) < R1 ? &hint2A[(row) * HROW2]              \
                                        : &hint2B[((row) - R1) * HROW2])
    if (r0v + 13 < R1) {        // warps 0..2: rows entirely in hintA
        VPASS_LOOP(ROWPTR_A)
    } else {                    // warps 3..7: mixed A/B rows
        VPASS_LOOP(ROWPTR_MIX)
    }

    const float C1 = 1e-4f;
    const float C2 = 9e-4f;
    float lsum = 0.f;
    #pragma unroll
    for (int o = 0; o < 4; ++o) {
        float muF = __low2float (acc[0][o]);
        float mu1 = __high2float(acc[0][o]);
        float mu2 = __low2float (acc[1][o]);
        float eFF = __high2float(acc[1][o]);
        float e11 = __low2float (acc[2][o]);
        float e22 = __high2float(acc[2][o]);
        float eF1 = __low2float (acc[3][o]);
        float eF2 = __high2float(acc[3][o]);

        float mFF = muF*muF, m11 = mu1*mu1, m22 = mu2*mu2;
        float pF1 = muF*mu1, pF2 = muF*mu2;

        float sF  = eFF - mFF;
        float s11 = e11 - m11;
        float s22 = e22 - m22;
        float c1v = eF1 - pF1;
        float c2v = eF2 - pF2;

        float num1 = (2.f*pF1 + C1) * (2.f*c1v + C2);
        float den1 = (mFF + m11 + C1) * (sF + s11 + C2);
        float num2 = (2.f*pF2 + C1) * (2.f*c2v + C2);
        float den2 = (mFF + m22 + C1) * (sF + s22 + C2);

        lsum += __fdividef(num1*den2 + num2*den1, den1*den2);
    }

    // ---- Reduction: warp shuffle -> block -> Q32 atomic (48 slots) --------
    #pragma unroll
    for (int off = 16; off > 0; off >>= 1)
        lsum += __shfl_xor_sync(0xffffffffu, lsum, off);

    __shared__ float     warpsum[8];
    __shared__ int       lastflag;
    __shared__ long long fin[2];
    if (lane == 0) warpsum[wid] = lsum;
    __syncthreads();
    if (tid == 0) {
        double s = 0.0;
        #pragma unroll
        for (int i = 0; i < 8; ++i) s += (double)warpsum[i];
        long long q = __double2ll_rn(s * FPSCALE);
        atomicAdd(&g_accs[bz], (u64)q);
        __threadfence();
        unsigned ticket = atomicInc(&g_count, NBLOCKS - 1);
        lastflag = (ticket == NBLOCKS - 1);
    }
    __syncthreads();

    if (lastflag) {
        long long v = 0;
        if (tid < NPLANES)
            v = (long long)atomicExch(&g_accs[tid], 0ULL);
        if (wid < 2) {
            #pragma unroll
            for (int off = 16; off > 0; off >>= 1)
                v += __shfl_xor_sync(0xffffffffu, v, off);
            if (lane == 0) fin[wid] = v;
        }
        __syncthreads();
        if (tid == 0) {
            long long tot = fin[0] + fin[1];
            out[0] = (float)(1.0 - ((double)tot * (1.0/FPSCALE))
                                   / (2.0 * NTOT));
        }
    }
}

extern "C" void kernel_launch(void* const* d_in, const int* in_sizes, int n_in,
                              void* d_out, int out_size)
{
    const float* F  = (const float*)d_in[0];
    const float* S1 = (const float*)d_in[1];
    const float* S2 = (const float*)d_in[2];

    static bool attr_set = false;
    if (!attr_set) {
        cudaFuncSetAttribute(ssim_fused_kernel,
                             cudaFuncAttributeMaxDynamicSharedMemorySize,
                             SMEM_BYTES);
        attr_set = true;
    }

    dim3 grid(GX, GY, NPLANES);
    ssim_fused_kernel<<<grid, NTHREADS, SMEM_BYTES>>>(F, S1, S2, (float*)d_out);
}

// round 16
// speedup vs baseline: 1.1126x; 1.1126x over previous
#include <cuda_runtime.h>
#include <cuda_fp16.h>

// ---------------------------------------------------------------------------
// SSIM fusion loss: 1 - (SSIM(f,s1)+SSIM(f,s2))/2, single fused kernel.
// 5 CTAs/SM. R13 structure with bank-conflict-free raw layout: RP=45/RROW=181
// (odd padding -> halo stores spread over all 4 bank residue classes; hpass
// loads conflict-free via LDS.32). Hint base padded to 16B. Bit-exact vs R13.
// ---------------------------------------------------------------------------

#define IMH 512
#define IMW 512
#define TW 32
#define TH 32
#define EXT 42
#define RP 45                    // cols per raw pair-plane (half2 units, padded)
#define RROW 181                 // raw row stride in half2 (odd: bank scatter)
#define HROW2 144                // hint row stride in half2 (4 pairs * 36)
#define PST2 36                  // half2 per pair within a hint row
#define R1 24                    // phase-A hint rows (0..23)
#define RAW_H2 7604              // hint base in half2: 42*181=7602, +2 pad ->
                                 // byte offset 30416, 16B-aligned for STS.128
#define NTHREADS 256
#define GX 16
#define GY 16
#define NPLANES 48
#define NBLOCKS (GX*GY*NPLANES)
#define NTOT 12582912.0
#define FPSCALE 4294967296.0
#define SMEM_BYTES (RAW_H2*4 + R1*HROW2*4)   // 30416 + 13824 = 44240 B

typedef unsigned long long u64;

__device__ u64      g_accs[NPLANES];
__device__ unsigned g_count = 0u;

// Gaussian weights (sigma=1.5, 11 taps, normalized) as pure literals.
#define W0f 0.00102838f
#define W1f 0.00759876f
#define W2f 0.03600077f
#define W3f 0.10936069f
#define W4f 0.21300554f
#define W5f 0.26601173f
#define WW(j) ( (j)==5 ? W5f : ((j)==4||(j)==6) ? W4f : ((j)==3||(j)==7) ? W3f \
              : ((j)==2||(j)==8) ? W2f : ((j)==1||(j)==9) ? W1f : W0f )

// half2 11-tap horizontal blur of one raw row (4 pair-planes), 4 output cols
// per plane, stored plane-major (one STS.128 per plane) exactly as R13.
// Loads are scalar LDS.32 (odd row stride -> no 16B alignment guarantee);
// 15 loads/plane, conflict-free by residue-class construction.
#define HPASS_H2(RAWBASE, HBASE)                                              \
{                                                                             \
    _Pragma("unroll")                                                         \
    for (int p = 0; p < 4; ++p) {                                             \
        __half2 v[15];                                                        \
        _Pragma("unroll")                                                     \
        for (int k = 0; k < 15; ++k)                                          \
            v[k] = raw2[(RAWBASE) + p*RP + c0 + k];                           \
        __half2 acc[4];                                                       \
        _Pragma("unroll")                                                     \
        for (int o = 0; o < 4; ++o) {                                         \
            __half2 s = __hmul2(wh[0], __hadd2(v[o+0], v[o+10]));             \
            _Pragma("unroll")                                                 \
            for (int j = 1; j < 5; ++j)                                       \
                s = __hfma2(wh[j], __hadd2(v[o+j], v[o+10-j]), s);            \
            acc[o] = __hfma2(wh[5], v[o+5], s);                               \
        }                                                                     \
        *reinterpret_cast<uint4*>(&hintS[(HBASE) + p*PST2 + c0]) =            \
            *reinterpret_cast<uint4*>(acc);                                   \
    }                                                                         \
}

// vpass accumulation over 14 hint rows starting at r0v (R13 structure, LDS.32).
#define VPASS_LOOP(ROWPTR)                                                    \
    _Pragma("unroll")                                                         \
    for (int jj = 0; jj < 14; ++jj) {                                         \
        const int row = r0v + jj;                                             \
        const __half2* rowp = ROWPTR(row);                                    \
        __half2 v[4];                                                         \
        _Pragma("unroll")                                                     \
        for (int p = 0; p < 4; ++p)                                           \
            v[p] = rowp[p * PST2 + col];                                      \
        _Pragma("unroll")                                                     \
        for (int o = 0; o < 4; ++o) {                                         \
            const int j = jj - o;                                             \
            if (j >= 0 && j < 11) {                                           \
                const __half2 w = wh[(j < 6) ? j : (10 - j)];                 \
                _Pragma("unroll")                                             \
                for (int p = 0; p < 4; ++p)                                   \
                    acc[p][o] = __hfma2(w, v[p], acc[p][o]);                  \
            }                                                                 \
        }                                                                     \
    }

__global__ __launch_bounds__(NTHREADS, 5)
void ssim_fused_kernel(const float* __restrict__ F,
                       const float* __restrict__ S1,
                       const float* __restrict__ S2,
                       float* __restrict__ out)
{
    extern __shared__ float smemf[];
    __half2* raw2   = reinterpret_cast<__half2*>(smemf);      // [42][4][45]+pad
    __half2* hint2A = raw2 + RAW_H2;                          // rows 0..23
    __half2* hint2B = raw2;                                   // rows 24..41 (alias)

    const int tid  = threadIdx.x;
    const int wid  = tid >> 5;
    const int lane = tid & 31;

    const int bx = blockIdx.x, by = blockIdx.y, bz = blockIdx.z;
    const int plane = bz * (IMH * IMW);
    const int y0 = by * TH - 5;

    // fp16 (w,w) weights, 6 unique — used by both passes
    __half2 wh[6];
    #pragma unroll
    for (int j = 0; j < 6; ++j) wh[j] = __floats2half2_rn(WW(j), WW(j));

    // ---- Halo load: 42 rows x 12 float4 chunks; build 4 half2 pair-planes -
    for (int i = tid; i < EXT * 12; i += NTHREADS) {
        const int q  = i % 12;
        const int r  = i / 12;
        const int gy = y0 + r;
        const int gx0 = bx * TW - 8 + q * 4;
        const bool ok = (gy >= 0) && (gy < IMH) && (gx0 >= 0) && (gx0 <= IMW - 4);

        float4 vf = make_float4(0.f,0.f,0.f,0.f);
        float4 va = vf, vb = vf;
        if (ok) {
            const int off = plane + gy * IMW + gx0;
            vf = *reinterpret_cast<const float4*>(F  + off);
            va = *reinterpret_cast<const float4*>(S1 + off);
            vb = *reinterpret_cast<const float4*>(S2 + off);
        }
        const float ff[4] = {vf.x, vf.y, vf.z, vf.w};
        const float fa[4] = {va.x, va.y, va.z, va.w};
        const float fb[4] = {vb.x, vb.y, vb.z, vb.w};

        const int cb = q * 4 - 3;
        #pragma unroll
        for (int t = 0; t < 4; ++t) {
            const int c = cb + t;
            if (c >= 0 && c < EXT) {
                const float f = ff[t], a = fa[t], b = fb[t];
                __half2 h0  = __floats2half2_rn(f, a);
                __half2 h1  = __floats2half2_rn(b, f * f);
                __half2 hab = __floats2half2_rn(a, b);
                __half2 hff = __floats2half2_rn(f, f);
                __half2 h2  = __hmul2(hab, hab);
                __half2 h3  = __hmul2(hff, hab);
                raw2[r*RROW + 0*RP + c] = h0;
                raw2[r*RROW + 1*RP + c] = h1;
                raw2[r*RROW + 2*RP + c] = h2;
                raw2[r*RROW + 3*RP + c] = h3;
            }
        }
    }
    __syncthreads();

    // ---- Horizontal pass, phase A: rows 0..23 -> hintA --------------------
    if (tid < R1 * 8) {
        const int r  = tid >> 3;
        const int c0 = (tid & 7) * 4;
        __half2* hintS = hint2A;
        HPASS_H2(r * RROW, r * HROW2)
    }
    __syncthreads();

    // ---- Phase B: rows 24..41 -> hintB at smem[0] (overlays raw rows <=13)
    if (tid < (EXT - R1) * 8) {
        const int rr = tid >> 3;            // 0..17 -> row 24+rr
        const int c0 = (tid & 7) * 4;
        __half2* hintS = hint2B;
        HPASS_H2((R1 + rr) * RROW, rr * HROW2)
    }
    __syncthreads();

    // ---- Vertical pass (half2/HFMA2) + SSIM: thread = 1 col x 4 rows ------
    const int col = lane;
    const int r0v = wid * 4;

    __half2 acc[4][4];  // [pair][out]
    #pragma unroll
    for (int p = 0; p < 4; ++p)
        #pragma unroll
        for (int o = 0; o < 4; ++o) acc[p][o] = __floats2half2_rn(0.f, 0.f);

    #define ROWPTR_A(row)   (&hint2A[(row) * HROW2])
    #define ROWPTR_MIX(row) ((row) < R1 ? &hint2A[(row) * HROW2]              \
                                        : &hint2B[((row) - R1) * HROW2])
    if (r0v + 13 < R1) {        // warps 0..2: rows entirely in hintA
        VPASS_LOOP(ROWPTR_A)
    } else {                    // warps 3..7: mixed A/B rows
        VPASS_LOOP(ROWPTR_MIX)
    }

    const float C1 = 1e-4f;
    const float C2 = 9e-4f;
    float lsum = 0.f;
    #pragma unroll
    for (int o = 0; o < 4; ++o) {
        float muF = __low2float (acc[0][o]);
        float mu1 = __high2float(acc[0][o]);
        float mu2 = __low2float (acc[1][o]);
        float eFF = __high2float(acc[1][o]);
        float e11 = __low2float (acc[2][o]);
        float e22 = __high2float(acc[2][o]);
        float eF1 = __low2float (acc[3][o]);
        float eF2 = __high2float(acc[3][o]);

        float mFF = muF*muF, m11 = mu1*mu1, m22 = mu2*mu2;
        float pF1 = muF*mu1, pF2 = muF*mu2;

        float sF  = eFF - mFF;
        float s11 = e11 - m11;
        float s22 = e22 - m22;
        float c1v = eF1 - pF1;
        float c2v = eF2 - pF2;

        float num1 = (2.f*pF1 + C1) * (2.f*c1v + C2);
        float den1 = (mFF + m11 + C1) * (sF + s11 + C2);
        float num2 = (2.f*pF2 + C1) * (2.f*c2v + C2);
        float den2 = (mFF + m22 + C1) * (sF + s22 + C2);

        lsum += __fdividef(num1*den2 + num2*den1, den1*den2);
    }

    // ---- Reduction: warp shuffle -> block -> Q32 atomic (48 slots) --------
    #pragma unroll
    for (int off = 16; off > 0; off >>= 1)
        lsum += __shfl_xor_sync(0xffffffffu, lsum, off);

    __shared__ float     warpsum[8];
    __shared__ int       lastflag;
    __shared__ long long fin[2];
    if (lane == 0) warpsum[wid] = lsum;
    __syncthreads();
    if (tid == 0) {
        double s = 0.0;
        #pragma unroll
        for (int i = 0; i < 8; ++i) s += (double)warpsum[i];
        long long q = __double2ll_rn(s * FPSCALE);
        atomicAdd(&g_accs[bz], (u64)q);
        __threadfence();
        unsigned ticket = atomicInc(&g_count, NBLOCKS - 1);
        lastflag = (ticket == NBLOCKS - 1);
    }
    __syncthreads();

    if (lastflag) {
        long long v = 0;
        if (tid < NPLANES)
            v = (long long)atomicExch(&g_accs[tid], 0ULL);
        if (wid < 2) {
            #pragma unroll
            for (int off = 16; off > 0; off >>= 1)
                v += __shfl_xor_sync(0xffffffffu, v, off);
            if (lane == 0) fin[wid] = v;
        }
        __syncthreads();
        if (tid == 0) {
            long long tot = fin[0] + fin[1];
            out[0] = (float)(1.0 - ((double)tot * (1.0/FPSCALE))
                                   / (2.0 * NTOT));
        }
    }
}

extern "C" void kernel_launch(void* const* d_in, const int* in_sizes, int n_in,
                              void* d_out, int out_size)
{
    const float* F  = (const float*)d_in[0];
    const float* S1 = (const float*)d_in[1];
    const float* S2 = (const float*)d_in[2];

    static bool attr_set = false;
    if (!attr_set) {
        cudaFuncSetAttribute(ssim_fused_kernel,
                             cudaFuncAttributeMaxDynamicSharedMemorySize,
                             SMEM_BYTES);
        attr_set = true;
    }

    dim3 grid(GX, GY, NPLANES);
    ssim_fused_kernel<<<grid, NTHREADS, SMEM_BYTES>>>(F, S1, S2, (float*)d_out);
}

// round 17
// speedup vs baseline: 1.1443x; 1.0285x over previous
#include <cuda_runtime.h>
#include <cuda_fp16.h>

// ---------------------------------------------------------------------------
// SSIM fusion loss: 1 - (SSIM(f,s1)+SSIM(f,s2))/2, single fused kernel.
// 5 CTAs/SM. Raw window origin at bx*32-8 so halo cols are 16B-aligned:
// halo stores are STS.128 (near-even granule spread), hpass loads are 5x
// LDS.128/plane (perfect granule spread). RP=48/RROW=196. Bit-exact vs R16.
// ---------------------------------------------------------------------------

#define IMH 512
#define IMW 512
#define TW 32
#define TH 32
#define EXT 42
#define RP 48                    // cols per raw pair-plane (half2, 16B mult)
#define RROW 196                 // raw row stride in half2 (R4=49, bank scatter)
#define HROW2 144                // hint row stride in half2 (4 pairs * 36)
#define PST2 36                  // half2 per pair within a hint row
#define R1 23                    // phase-A hint rows (0..22)
#define RAW_H2 8232              // hint base in half2 = 42*196 (32928 B, 16B ok)
#define NTHREADS 256
#define GX 16
#define GY 16
#define NPLANES 48
#define NBLOCKS (GX*GY*NPLANES)
#define NTOT 12582912.0
#define FPSCALE 4294967296.0
#define SMEM_BYTES (RAW_H2*4 + R1*HROW2*4)   // 32928 + 13248 = 46176 B

typedef unsigned long long u64;

__device__ u64      g_accs[NPLANES];
__device__ unsigned g_count = 0u;

// Gaussian weights (sigma=1.5, 11 taps, normalized) as pure literals.
#define W0f 0.00102838f
#define W1f 0.00759876f
#define W2f 0.03600077f
#define W3f 0.10936069f
#define W4f 0.21300554f
#define W5f 0.26601173f
#define WW(j) ( (j)==5 ? W5f : ((j)==4||(j)==6) ? W4f : ((j)==3||(j)==7) ? W3f \
              : ((j)==2||(j)==8) ? W2f : ((j)==1||(j)==9) ? W1f : W0f )

// half2 11-tap horizontal blur of one raw row (4 pair-planes), 4 output cols
// per plane. Raw col origin is gx = bx*32-8, so output x=c0+o taps
// v[o+3+j], j=0..10, from a 20-half2 window loaded as 5 LDS.128.
// Math (values and order) identical to R16.
#define HPASS_H2(RAWBASE, HBASE)                                              \
{                                                                             \
    _Pragma("unroll")                                                         \
    for (int p = 0; p < 4; ++p) {                                             \
        __half2 v[20];                                                        \
        _Pragma("unroll")                                                     \
        for (int k = 0; k < 5; ++k)                                           \
            *reinterpret_cast<uint4*>(&v[4*k]) =                              \
                *reinterpret_cast<const uint4*>(&raw2[(RAWBASE) + p*RP + c0 + 4*k]); \
        __half2 acc[4];                                                       \
        _Pragma("unroll")                                                     \
        for (int o = 0; o < 4; ++o) {                                         \
            __half2 s = __hmul2(wh[0], __hadd2(v[o+3+0], v[o+3+10]));         \
            _Pragma("unroll")                                                 \
            for (int j = 1; j < 5; ++j)                                       \
                s = __hfma2(wh[j], __hadd2(v[o+3+j], v[o+3+10-j]), s);        \
            acc[o] = __hfma2(wh[5], v[o+3+5], s);                             \
        }                                                                     \
        *reinterpret_cast<uint4*>(&hintS[(HBASE) + p*PST2 + c0]) =            \
            *reinterpret_cast<uint4*>(acc);                                   \
    }                                                                         \
}

// vpass accumulation over 14 hint rows starting at r0v (R16 structure).
#define VPASS_LOOP(ROWPTR)                                                    \
    _Pragma("unroll")                                                         \
    for (int jj = 0; jj < 14; ++jj) {                                         \
        const int row = r0v + jj;                                             \
        const __half2* rowp = ROWPTR(row);                                    \
        __half2 v[4];                                                         \
        _Pragma("unroll")                                                     \
        for (int p = 0; p < 4; ++p)                                           \
            v[p] = rowp[p * PST2 + col];                                      \
        _Pragma("unroll")                                                     \
        for (int o = 0; o < 4; ++o) {                                         \
            const int j = jj - o;                                             \
            if (j >= 0 && j < 11) {                                           \
                const __half2 w = wh[(j < 6) ? j : (10 - j)];                 \
                _Pragma("unroll")                                             \
                for (int p = 0; p < 4; ++p)                                   \
                    acc[p][o] = __hfma2(w, v[p], acc[p][o]);                  \
            }                                                                 \
        }                                                                     \
    }

__global__ __launch_bounds__(NTHREADS, 5)
void ssim_fused_kernel(const float* __restrict__ F,
                       const float* __restrict__ S1,
                       const float* __restrict__ S2,
                       float* __restrict__ out)
{
    extern __shared__ float smemf[];
    __half2* raw2   = reinterpret_cast<__half2*>(smemf);      // [42][4][48]+pad
    __half2* hint2A = raw2 + RAW_H2;                          // rows 0..22
    __half2* hint2B = raw2;                                   // rows 23..41 (alias)

    const int tid  = threadIdx.x;
    const int wid  = tid >> 5;
    const int lane = tid & 31;

    const int bx = blockIdx.x, by = blockIdx.y, bz = blockIdx.z;
    const int plane = bz * (IMH * IMW);
    const int y0 = by * TH - 5;

    // fp16 (w,w) weights, 6 unique — used by both passes
    __half2 wh[6];
    #pragma unroll
    for (int j = 0; j < 6; ++j) wh[j] = __floats2half2_rn(WW(j), WW(j));

    // ---- Halo load: 42 rows x 12 float4 chunks -> 4 half2 pair-planes -----
    // Raw col c' = 4q+t (16B-aligned); one STS.128 per (chunk, plane).
    for (int i = tid; i < EXT * 12; i += NTHREADS) {
        const int q  = i % 12;
        const int r  = i / 12;
        const int gy = y0 + r;
        const int gx0 = bx * TW - 8 + q * 4;
        const bool ok = (gy >= 0) && (gy < IMH) && (gx0 >= 0) && (gx0 <= IMW - 4);

        float4 vf = make_float4(0.f,0.f,0.f,0.f);
        float4 va = vf, vb = vf;
        if (ok) {
            const int off = plane + gy * IMW + gx0;
            vf = *reinterpret_cast<const float4*>(F  + off);
            va = *reinterpret_cast<const float4*>(S1 + off);
            vb = *reinterpret_cast<const float4*>(S2 + off);
        }
        const float ff[4] = {vf.x, vf.y, vf.z, vf.w};
        const float fa[4] = {va.x, va.y, va.z, va.w};
        const float fb[4] = {vb.x, vb.y, vb.z, vb.w};

        __half2 h0[4], h1[4], h2[4], h3[4];
        #pragma unroll
        for (int t = 0; t < 4; ++t) {
            const float f = ff[t], a = fa[t], b = fb[t];
            h0[t] = __floats2half2_rn(f, a);
            h1[t] = __floats2half2_rn(b, f * f);
            __half2 hab = __floats2half2_rn(a, b);
            __half2 hff = __floats2half2_rn(f, f);
            h2[t] = __hmul2(hab, hab);
            h3[t] = __hmul2(hff, hab);
        }
        const int cb = r * RROW + q * 4;
        *reinterpret_cast<uint4*>(&raw2[cb + 0*RP]) = *reinterpret_cast<uint4*>(h0);
        *reinterpret_cast<uint4*>(&raw2[cb + 1*RP]) = *reinterpret_cast<uint4*>(h1);
        *reinterpret_cast<uint4*>(&raw2[cb + 2*RP]) = *reinterpret_cast<uint4*>(h2);
        *reinterpret_cast<uint4*>(&raw2[cb + 3*RP]) = *reinterpret_cast<uint4*>(h3);
    }
    __syncthreads();

    // ---- Horizontal pass, phase A: rows 0..22 -> hintA --------------------
    if (tid < R1 * 8) {
        const int r  = tid >> 3;
        const int c0 = (tid & 7) * 4;
        __half2* hintS = hint2A;
        HPASS_H2(r * RROW, r * HROW2)
    }
    __syncthreads();

    // ---- Phase B: rows 23..41 -> hintB at smem[0] (overlays raw rows <=13)
    if (tid < (EXT - R1) * 8) {
        const int rr = tid >> 3;            // 0..18 -> row 23+rr
        const int c0 = (tid & 7) * 4;
        __half2* hintS = hint2B;
        HPASS_H2((R1 + rr) * RROW, rr * HROW2)
    }
    __syncthreads();

    // ---- Vertical pass (half2/HFMA2) + SSIM: thread = 1 col x 4 rows ------
    const int col = lane;
    const int r0v = wid * 4;

    __half2 acc[4][4];  // [pair][out]
    #pragma unroll
    for (int p = 0; p < 4; ++p)
        #pragma unroll
        for (int o = 0; o < 4; ++o) acc[p][o] = __floats2half2_rn(0.f, 0.f);

    #define ROWPTR_A(row)   (&hint2A[(row) * HROW2])
    #define ROWPTR_B(row)   (&hint2B[((row) - R1) * HROW2])
    #define ROWPTR_MIX(row) ((row) < R1 ? &hint2A[(row) * HROW2]              \
                                        : &hint2B[((row) - R1) * HROW2])
    if (r0v + 13 < R1) {            // warps 0..2: rows entirely in hintA
        VPASS_LOOP(ROWPTR_A)
    } else if (r0v >= R1) {         // warps 6..7: rows entirely in hintB
        VPASS_LOOP(ROWPTR_B)
    } else {                        // warps 3..5: mixed A/B rows
        VPASS_LOOP(ROWPTR_MIX)
    }

    const float C1 = 1e-4f;
    const float C2 = 9e-4f;
    float lsum = 0.f;
    #pragma unroll
    for (int o = 0; o < 4; ++o) {
        float muF = __low2float (acc[0][o]);
        float mu1 = __high2float(acc[0][o]);
        float mu2 = __low2float (acc[1][o]);
        float eFF = __high2float(acc[1][o]);
        float e11 = __low2float (acc[2][o]);
        float e22 = __high2float(acc[2][o]);
        float eF1 = __low2float (acc[3][o]);
        float eF2 = __high2float(acc[3][o]);

        float mFF = muF*muF, m11 = mu1*mu1, m22 = mu2*mu2;
        float pF1 = muF*mu1, pF2 = muF*mu2;

        float sF  = eFF - mFF;
        float s11 = e11 - m11;
        float s22 = e22 - m22;
        float c1v = eF1 - pF1;
        float c2v = eF2 - pF2;

        float num1 = (2.f*pF1 + C1) * (2.f*c1v + C2);
        float den1 = (mFF + m11 + C1) * (sF + s11 + C2);
        float num2 = (2.f*pF2 + C1) * (2.f*c2v + C2);
        float den2 = (mFF + m22 + C1) * (sF + s22 + C2);

        lsum += __fdividef(num1*den2 + num2*den1, den1*den2);
    }

    // ---- Reduction: warp shuffle -> block -> Q32 atomic (48 slots) --------
    #pragma unroll
    for (int off = 16; off > 0; off >>= 1)
        lsum += __shfl_xor_sync(0xffffffffu, lsum, off);

    __shared__ float     warpsum[8];
    __shared__ int       lastflag;
    __shared__ long long fin[2];
    if (lane == 0) warpsum[wid] = lsum;
    __syncthreads();
    if (tid == 0) {
        double s = 0.0;
        #pragma unroll
        for (int i = 0; i < 8; ++i) s += (double)warpsum[i];
        long long q = __double2ll_rn(s * FPSCALE);
        atomicAdd(&g_accs[bz], (u64)q);
        __threadfence();
        unsigned ticket = atomicInc(&g_count, NBLOCKS - 1);
        lastflag = (ticket == NBLOCKS - 1);
    }
    __syncthreads();

    if (lastflag) {
        long long v = 0;
        if (tid < NPLANES)
            v = (long long)atomicExch(&g_accs[tid], 0ULL);
        if (wid < 2) {
            #pragma unroll
            for (int off = 16; off > 0; off >>= 1)
                v += __shfl_xor_sync(0xffffffffu, v, off);
            if (lane == 0) fin[wid] = v;
        }
        __syncthreads();
        if (tid == 0) {
            long long tot = fin[0] + fin[1];
            out[0] = (float)(1.0 - ((double)tot * (1.0/FPSCALE))
                                   / (2.0 * NTOT));
        }
    }
}

extern "C" void kernel_launch(void* const* d_in, const int* in_sizes, int n_in,
                              void* d_out, int out_size)
{
    const float* F  = (const float*)d_in[0];
    const float* S1 = (const float*)d_in[1];
    const float* S2 = (const float*)d_in[2];

    static bool attr_set = false;
    if (!attr_set) {
        cudaFuncSetAttribute(ssim_fused_kernel,
                             cudaFuncAttributeMaxDynamicSharedMemorySize,
                             SMEM_BYTES);
        attr_set = true;
    }

    dim3 grid(GX, GY, NPLANES);
    ssim_fused_kernel<<<grid, NTHREADS, SMEM_BYTES>>>(F, S1, S2, (float*)d_out);
}